// round 2
// baseline (speedup 1.0000x reference)
#include <cuda_runtime.h>
#include <math_constants.h>

// Chamfer 1D: N = M = 16384 fp32.
// out = 0.5 * sum_i min_j |x_i - y_j| / N + 0.5 * sum_j min_i |y_j - x_i| / M

#define CN      16384
#define TPB     256
#define CHUNK   2048
#define NCHUNK  (CN / CHUNK)      // 8
#define NXBLK   (CN / TPB)        // 64

// Per-element running minima (bit patterns of nonnegative floats, so unsigned
// atomicMin gives float min). dir 0: min over y for each x; dir 1: min over x
// for each y.
__device__ unsigned g_min[2][CN];

__global__ void init_min_kernel() {
    int i = blockIdx.x * blockDim.x + threadIdx.x;
    if (i < CN) {
        g_min[0][i] = 0x7F800000u;   // +inf
        g_min[1][i] = 0x7F800000u;
    }
}

__global__ void chamfer_pass_kernel(const float* __restrict__ x,
                                    const float* __restrict__ y) {
    __shared__ float sB[CHUNK];

    const int dir = blockIdx.z;
    const float* __restrict__ A = dir ? y : x;  // array we take mins FOR
    const float* __restrict__ B = dir ? x : y;  // array we take mins OVER

    const int i = blockIdx.x * TPB + threadIdx.x;
    const float av = A[i];

    // Stage this block's B-chunk into shared (vectorized).
    const int base = blockIdx.y * CHUNK;
    float4* s4 = reinterpret_cast<float4*>(sB);
    const float4* b4 = reinterpret_cast<const float4*>(B + base);
    #pragma unroll
    for (int k = threadIdx.x; k < CHUNK / 4; k += TPB) {
        s4[k] = b4[k];
    }
    __syncthreads();

    // 4 independent accumulators to break the FMNMX dependency chain.
    float m0 = CUDART_INF_F, m1 = CUDART_INF_F;
    float m2 = CUDART_INF_F, m3 = CUDART_INF_F;

    const float4* sv = reinterpret_cast<const float4*>(sB);
    #pragma unroll 8
    for (int k = 0; k < CHUNK / 4; k++) {
        float4 v = sv[k];                 // LDS.128, broadcast (no conflicts)
        m0 = fminf(m0, fabsf(av - v.x));
        m1 = fminf(m1, fabsf(av - v.y));
        m2 = fminf(m2, fabsf(av - v.z));
        m3 = fminf(m3, fabsf(av - v.w));
    }
    float m = fminf(fminf(m0, m1), fminf(m2, m3));

    atomicMin(&g_min[dir][i], __float_as_uint(m));
}

// Deterministic single-block reduction: fixed per-thread accumulation order +
// fixed shared-memory tree, so every run produces bit-identical output.
__global__ void chamfer_reduce_kernel(float* __restrict__ out) {
    __shared__ float s[TPB];
    float acc = 0.0f;
    for (int k = threadIdx.x; k < CN; k += TPB)
        acc += __uint_as_float(g_min[0][k]);
    for (int k = threadIdx.x; k < CN; k += TPB)
        acc += __uint_as_float(g_min[1][k]);
    s[threadIdx.x] = acc;
    __syncthreads();
    #pragma unroll
    for (int stride = TPB / 2; stride > 0; stride >>= 1) {
        if (threadIdx.x < stride) s[threadIdx.x] += s[threadIdx.x + stride];
        __syncthreads();
    }
    if (threadIdx.x == 0) {
        // alpha = 0.5, n = m = CN:  0.5 * (sum_x + sum_y) / CN
        out[0] = 0.5f * s[0] / (float)CN;
    }
}

extern "C" void kernel_launch(void* const* d_in, const int* in_sizes, int n_in,
                              void* d_out, int out_size) {
    const float* x = (const float*)d_in[0];   // inputs  [16384] f32
    const float* y = (const float*)d_in[1];   // targets [16384] f32
    float* out = (float*)d_out;

    init_min_kernel<<<(CN + TPB - 1) / TPB, TPB>>>();

    dim3 grid(NXBLK, NCHUNK, 2);
    chamfer_pass_kernel<<<grid, TPB>>>(x, y);

    chamfer_reduce_kernel<<<1, TPB>>>(out);
}

// round 3
// speedup vs baseline: 1.3102x; 1.3102x over previous
#include <cuda_runtime.h>
#include <math_constants.h>

// Chamfer 1D via bucketed nearest-neighbor search. N = M = 16384 fp32.
// out = 0.5 * sum_i min_j |x_i - y_j| / N + 0.5 * sum_j min_i |y_j - x_i| / N

#define CN   16384
#define NB   4096          // buckets
#define TPB  256

// Persistent device scratch (no allocations allowed).
// lo/hi keys: monotone atomic min/max -> idempotent across graph replays,
// so static init is sufficient (values converge on the correctness run and
// never change afterwards for fixed inputs).
__device__ unsigned g_lo_key = 0xFFFFFFFFu;
__device__ unsigned g_hi_key = 0x00000000u;
__device__ unsigned g_hist[2][NB];
__device__ unsigned g_off[2][NB + 1];
__device__ unsigned g_cur[2][NB];
__device__ float    g_sorted[2][CN];

// Order-preserving float<->uint key
__device__ __forceinline__ unsigned f2key(float f) {
    unsigned u = __float_as_uint(f);
    return u ^ ((u >> 31) ? 0xFFFFFFFFu : 0x80000000u);
}
__device__ __forceinline__ float key2f(unsigned k) {
    unsigned u = k ^ ((k >> 31) ? 0x80000000u : 0xFFFFFFFFu);
    return __uint_as_float(u);
}

__device__ __forceinline__ int bucket_of(float v, float lo, float invw) {
    int b = (int)((v - lo) * invw);
    return min(NB - 1, max(0, b));
}

// K1: zero histograms + out, global min/max over x and y (warp-reduced atomics)
__global__ void k1_minmax_zero(const float* __restrict__ x,
                               const float* __restrict__ y,
                               float* __restrict__ out) {
    int i = blockIdx.x * blockDim.x + threadIdx.x;
    if (i < NB) { g_hist[0][i] = 0u; g_hist[1][i] = 0u; }
    if (i == 0) out[0] = 0.0f;

    unsigned kx = f2key(x[i]);
    unsigned ky = f2key(y[i]);
    unsigned kmin = min(kx, ky);
    unsigned kmax = max(kx, ky);
    kmin = __reduce_min_sync(0xFFFFFFFFu, kmin);
    kmax = __reduce_max_sync(0xFFFFFFFFu, kmax);
    if ((threadIdx.x & 31) == 0) {
        atomicMin(&g_lo_key, kmin);
        atomicMax(&g_hi_key, kmax);
    }
}

// K2: histogram both arrays
__global__ void k2_hist(const float* __restrict__ x,
                        const float* __restrict__ y) {
    float lo = key2f(g_lo_key);
    float hi = key2f(g_hi_key);
    float invw = (hi > lo) ? (float)NB / (hi - lo) : 0.0f;
    int i = blockIdx.x * blockDim.x + threadIdx.x;
    atomicAdd(&g_hist[0][bucket_of(x[i], lo, invw)], 1u);
    atomicAdd(&g_hist[1][bucket_of(y[i], lo, invw)], 1u);
}

// K3: single-block exclusive scan of both histograms -> offsets + cursors
__global__ void k3_scan() {
    __shared__ unsigned s[1024];
    const int t = threadIdx.x;
    #pragma unroll
    for (int a = 0; a < 2; a++) {
        unsigned v0 = g_hist[a][4 * t + 0];
        unsigned v1 = g_hist[a][4 * t + 1];
        unsigned v2 = g_hist[a][4 * t + 2];
        unsigned v3 = g_hist[a][4 * t + 3];
        unsigned sum = v0 + v1 + v2 + v3;
        s[t] = sum;
        __syncthreads();
        // Hillis-Steele inclusive scan over 1024 chunk sums
        for (int d = 1; d < 1024; d <<= 1) {
            unsigned add = (t >= d) ? s[t - d] : 0u;
            __syncthreads();
            s[t] += add;
            __syncthreads();
        }
        unsigned base = s[t] - sum;   // exclusive prefix of this chunk
        unsigned o0 = base;
        unsigned o1 = o0 + v0;
        unsigned o2 = o1 + v1;
        unsigned o3 = o2 + v2;
        g_off[a][4 * t + 0] = o0;  g_cur[a][4 * t + 0] = o0;
        g_off[a][4 * t + 1] = o1;  g_cur[a][4 * t + 1] = o1;
        g_off[a][4 * t + 2] = o2;  g_cur[a][4 * t + 2] = o2;
        g_off[a][4 * t + 3] = o3;  g_cur[a][4 * t + 3] = o3;
        if (t == 1023) g_off[a][NB] = s[1023];   // == CN
        __syncthreads();
    }
}

// K4: counting-sort scatter (within-bucket order irrelevant -> replay-safe)
__global__ void k4_scatter(const float* __restrict__ x,
                           const float* __restrict__ y) {
    float lo = key2f(g_lo_key);
    float hi = key2f(g_hi_key);
    float invw = (hi > lo) ? (float)NB / (hi - lo) : 0.0f;
    int i = blockIdx.x * blockDim.x + threadIdx.x;
    {
        float v = x[i];
        unsigned p = atomicAdd(&g_cur[0][bucket_of(v, lo, invw)], 1u);
        g_sorted[0][p] = v;
    }
    {
        float v = y[i];
        unsigned p = atomicAdd(&g_cur[1][bucket_of(v, lo, invw)], 1u);
        g_sorted[1][p] = v;
    }
}

// K5: per-query outward ring search + block reduction + scaled atomicAdd
__global__ void k5_search(float* __restrict__ out) {
    const int gi = blockIdx.x * blockDim.x + threadIdx.x;   // 0 .. 2*CN-1
    const int dir = gi >= CN;            // 0: queries=x-sorted, cands=y-sorted
    const int i = gi - dir * CN;

    const float lo = key2f(g_lo_key);
    const float hi = key2f(g_hi_key);
    const float range = hi - lo;
    const float invw = (range > 0.0f) ? (float)NB / range : 0.0f;
    const float w = range * (1.0f / NB);

    const float* __restrict__ qArr = g_sorted[dir];
    const float* __restrict__ cArr = g_sorted[1 - dir];
    const unsigned* __restrict__ off = g_off[1 - dir];

    const float q = qArr[i];
    const int b = bucket_of(q, lo, invw);

    float best = CUDART_INF_F;
    for (unsigned k = off[b]; k < off[b + 1]; k++)
        best = fminf(best, fabsf(q - cArr[k]));

    int bl = b - 1, br = b + 1;
    bool goL = (bl >= 0), goR = (br < NB);
    while (goL || goR) {
        if (goL) {
            float gap = q - (lo + (float)(bl + 1) * w);  // >= true min dist in bucket bl
            if (gap >= best) {
                goL = false;
            } else {
                for (unsigned k = off[bl]; k < off[bl + 1]; k++)
                    best = fminf(best, fabsf(q - cArr[k]));
                if (--bl < 0) goL = false;
            }
        }
        if (goR) {
            float gap = (lo + (float)br * w) - q;
            if (gap >= best) {
                goR = false;
            } else {
                for (unsigned k = off[br]; k < off[br + 1]; k++)
                    best = fminf(best, fabsf(q - cArr[k]));
                if (++br >= NB) goR = false;
            }
        }
    }

    // Block sum of per-query minima, then one atomicAdd of the scaled partial.
    __shared__ float s[TPB];
    s[threadIdx.x] = best;
    __syncthreads();
    #pragma unroll
    for (int stride = TPB / 2; stride > 0; stride >>= 1) {
        if (threadIdx.x < stride) s[threadIdx.x] += s[threadIdx.x + stride];
        __syncthreads();
    }
    if (threadIdx.x == 0)
        atomicAdd(out, s[0] * (0.5f / (float)CN));
}

extern "C" void kernel_launch(void* const* d_in, const int* in_sizes, int n_in,
                              void* d_out, int out_size) {
    const float* x = (const float*)d_in[0];   // inputs  [16384] f32
    const float* y = (const float*)d_in[1];   // targets [16384] f32
    float* out = (float*)d_out;

    k1_minmax_zero<<<CN / TPB, TPB>>>(x, y, out);
    k2_hist<<<CN / TPB, TPB>>>(x, y);
    k3_scan<<<1, 1024>>>();
    k4_scatter<<<CN / TPB, TPB>>>(x, y);
    k5_search<<<2 * CN / TPB, TPB>>>(out);
}